// round 7
// baseline (speedup 1.0000x reference)
#include <cuda_runtime.h>
#include <cuda_fp16.h>
#include <cstdint>

#define N_NODES 50000
#define N_EDGES 800000
#define IN_CH 16
#define OUT_CH 16
#define M_TILE 128
#define NT_TILES (N_EDGES / M_TILE)   // 6250
#define THREADS 512
#define GRID 152

// ---- smem byte offsets ----
#define SM_W1   0        // [16][120] f16   = 3840
#define SM_W2   3840     // [112][120] f16  = 26880
#define SM_W3   30720    // [112][120] f16  = 26880
#define SM_W4   57600    // [112][264] f16  = 59136
#define SM_A0   116736   // [128][24] f16   = 6144
#define SM_H1   122880   // [128][120] f16  = 30720
#define SM_H2   153600   // [128][120] f16  = 30720
#define SM_XV   184320   // [128][17] f32   = 8704
#define SM_MSG  193024   // [128][17] f32   = 8704
#define SM_B1   201728   // [112] f32
#define SM_B2   202176
#define SM_B3   202624
#define SM_B4   203072   // [256] f32
#define SM_IDX  204096   // dst [128] int
#define SM_SRC  204608   // src [128] int
#define SMEM_BYTES 205120
#define W_ZERO_U32 (116736 / 4)

__device__ float g_agg[N_NODES * OUT_CH];
__device__ float g_cnt[N_NODES];

__device__ __forceinline__ uint32_t smem_u32(const void* p) {
    uint32_t a;
    asm("{ .reg .u64 t; cvta.to.shared.u64 t, %1; cvt.u32.u64 %0, t; }" : "=r"(a) : "l"(p));
    return a;
}

#define LDSM_X4(r, a) \
    asm volatile("ldmatrix.sync.aligned.m8n8.x4.shared.b16 {%0,%1,%2,%3}, [%4];" \
        : "=r"((r)[0]), "=r"((r)[1]), "=r"((r)[2]), "=r"((r)[3]) : "r"(a))
#define LDSM_X2T(r, a) \
    asm volatile("ldmatrix.sync.aligned.m8n8.x2.trans.shared.b16 {%0,%1}, [%2];" \
        : "=r"((r)[0]), "=r"((r)[1]) : "r"(a))
#define MMA16816(c, a, b) \
    asm volatile("mma.sync.aligned.m16n8k16.row.col.f32.f16.f16.f32 " \
        "{%0,%1,%2,%3},{%4,%5,%6,%7},{%8,%9},{%0,%1,%2,%3};" \
        : "+f"((c)[0]), "+f"((c)[1]), "+f"((c)[2]), "+f"((c)[3]) \
        : "r"((a)[0]), "r"((a)[1]), "r"((a)[2]), "r"((a)[3]), "r"((b)[0]), "r"((b)[1]))

__global__ void zero_kernel() {
    int total = N_NODES * OUT_CH;
    for (int i = blockIdx.x * blockDim.x + threadIdx.x; i < total; i += gridDim.x * blockDim.x) {
        g_agg[i] = 0.0f;
        if (i < N_NODES) g_cnt[i] = 0.0f;
    }
}

// Generic MLP layer: Hout = relu(Hin @ W + b), fp16 in/out, f32 accum.
template<int KSTEPS, int MAXNT>
__device__ __forceinline__ void layer_f16(
    const __half* __restrict__ Hin, int sIn,
    const __half* __restrict__ W, int sW,
    const float* __restrict__ bias,
    __half* __restrict__ Hout, int sOut,
    int nt0, int ntCnt, int mbase, int lane)
{
    const int grp = lane >> 2, tig = lane & 3;
    float acc[MAXNT][2][4];
    #pragma unroll
    for (int nt = 0; nt < MAXNT; nt++) {
        if (nt >= ntCnt) break;
        const int c = (nt0 + nt) * 8 + 2 * tig;
        const float b0 = bias[c], b1 = bias[c + 1];
        #pragma unroll
        for (int mt = 0; mt < 2; mt++) {
            acc[nt][mt][0] = b0; acc[nt][mt][1] = b1;
            acc[nt][mt][2] = b0; acc[nt][mt][3] = b1;
        }
    }
    const int arow = mbase + ((lane >> 3) & 1) * 8 + (lane & 7);
    const int acol = (lane >> 4) * 8;
    const int brow = lane & 15;
    #pragma unroll
    for (int k = 0; k < KSTEPS; k++) {
        const int k0 = k * 16;
        uint32_t a[2][4];
        #pragma unroll
        for (int mt = 0; mt < 2; mt++) {
            uint32_t aaddr = smem_u32(Hin + (arow + mt * 16) * sIn + k0 + acol);
            LDSM_X4(a[mt], aaddr);
        }
        #pragma unroll
        for (int nt = 0; nt < MAXNT; nt++) {
            if (nt >= ntCnt) break;
            const int n0 = (nt0 + nt) * 8;
            uint32_t b[2];
            uint32_t baddr = smem_u32(W + (k0 + brow) * sW + n0);
            LDSM_X2T(b, baddr);
            MMA16816(acc[nt][0], a[0], b);
            MMA16816(acc[nt][1], a[1], b);
        }
    }
    #pragma unroll
    for (int nt = 0; nt < MAXNT; nt++) {
        if (nt >= ntCnt) break;
        const int n0 = (nt0 + nt) * 8;
        #pragma unroll
        for (int mt = 0; mt < 2; mt++) {
            const int r0 = mbase + mt * 16 + grp;
            __half2 v0 = __floats2half2_rn(fmaxf(acc[nt][mt][0], 0.f), fmaxf(acc[nt][mt][1], 0.f));
            __half2 v1 = __floats2half2_rn(fmaxf(acc[nt][mt][2], 0.f), fmaxf(acc[nt][mt][3], 0.f));
            *(__half2*)(Hout + r0 * sOut + n0 + 2 * tig) = v0;
            *(__half2*)(Hout + (r0 + 8) * sOut + n0 + 2 * tig) = v1;
        }
    }
}

// Layer 4 (100->256, no relu) with fused einsum epilogue into MSG (smem atomics).
__device__ __forceinline__ void layer4_f16(
    const __half* __restrict__ Hin,
    const __half* __restrict__ W4h,
    const float* __restrict__ b4f,
    const float* __restrict__ XV,
    float* __restrict__ MSG,
    int q, int mbase, int lane)
{
    const int grp = lane >> 2, tig = lane & 3;
    float acc[8][2][4];
    #pragma unroll
    for (int nt = 0; nt < 8; nt++) {
        const int c = (q * 8 + nt) * 8 + 2 * tig;
        const float b0 = b4f[c], b1 = b4f[c + 1];
        #pragma unroll
        for (int mt = 0; mt < 2; mt++) {
            acc[nt][mt][0] = b0; acc[nt][mt][1] = b1;
            acc[nt][mt][2] = b0; acc[nt][mt][3] = b1;
        }
    }
    const int arow = mbase + ((lane >> 3) & 1) * 8 + (lane & 7);
    const int acol = (lane >> 4) * 8;
    const int brow = lane & 15;
    #pragma unroll
    for (int k = 0; k < 7; k++) {
        const int k0 = k * 16;
        uint32_t a[2][4];
        #pragma unroll
        for (int mt = 0; mt < 2; mt++) {
            uint32_t aaddr = smem_u32(Hin + (arow + mt * 16) * 120 + k0 + acol);
            LDSM_X4(a[mt], aaddr);
        }
        #pragma unroll
        for (int nt = 0; nt < 8; nt++) {
            const int n0 = (q * 8 + nt) * 8;
            uint32_t b[2];
            uint32_t baddr = smem_u32(W4h + (k0 + brow) * 264 + n0);
            LDSM_X2T(b, baddr);
            MMA16816(acc[nt][0], a[0], b);
            MMA16816(acc[nt][1], a[1], b);
        }
    }
    #pragma unroll
    for (int nt = 0; nt < 8; nt++) {
        const int c = (q * 8 + nt) * 8 + 2 * tig;   // even
        const int i = c >> 4, o = c & 15;
        #pragma unroll
        for (int mt = 0; mt < 2; mt++) {
            const int e0 = mbase + mt * 16 + grp, e1 = e0 + 8;
            const float xv0 = XV[e0 * 17 + i], xv1 = XV[e1 * 17 + i];
            atomicAdd(&MSG[e0 * 17 + o],     xv0 * acc[nt][mt][0]);
            atomicAdd(&MSG[e0 * 17 + o + 1], xv0 * acc[nt][mt][1]);
            atomicAdd(&MSG[e1 * 17 + o],     xv1 * acc[nt][mt][2]);
            atomicAdd(&MSG[e1 * 17 + o + 1], xv1 * acc[nt][mt][3]);
        }
    }
}

extern __shared__ char smem[];

__global__ void __launch_bounds__(THREADS, 1)
edge_kernel(const float* __restrict__ x,
            const int* __restrict__ ei,
            const float* __restrict__ ea,
            const float* __restrict__ W1, const float* __restrict__ b1,
            const float* __restrict__ W2, const float* __restrict__ b2,
            const float* __restrict__ W3, const float* __restrict__ b3,
            const float* __restrict__ W4, const float* __restrict__ b4)
{
    const int tid = threadIdx.x;
    const int wid = tid >> 5, lane = tid & 31;
    const int q = wid & 3, mbase = (wid >> 2) * 32;

    __half* W1h = (__half*)(smem + SM_W1);
    __half* W2h = (__half*)(smem + SM_W2);
    __half* W3h = (__half*)(smem + SM_W3);
    __half* W4h = (__half*)(smem + SM_W4);
    __half* A0h = (__half*)(smem + SM_A0);
    __half* H1h = (__half*)(smem + SM_H1);
    __half* H2h = (__half*)(smem + SM_H2);
    float*  XV  = (float*)(smem + SM_XV);
    float*  MSG = (float*)(smem + SM_MSG);
    float*  B1f = (float*)(smem + SM_B1);
    float*  B2f = (float*)(smem + SM_B2);
    float*  B3f = (float*)(smem + SM_B3);
    float*  B4f = (float*)(smem + SM_B4);
    int*    DSTi = (int*)(smem + SM_IDX);
    int*    SRCi = (int*)(smem + SM_SRC);

    // zero weight region (covers K/N zero-padding)
    for (int i = tid; i < W_ZERO_U32; i += THREADS) ((uint32_t*)smem)[i] = 0;
    __syncthreads();
    for (int i = tid; i < 8 * 100; i += THREADS) {
        int k = i / 100, n = i % 100;
        W1h[k * 120 + n] = __float2half(W1[i]);
    }
    for (int i = tid; i < 100 * 100; i += THREADS) {
        int k = i / 100, n = i % 100;
        W2h[k * 120 + n] = __float2half(W2[i]);
        W3h[k * 120 + n] = __float2half(W3[i]);
    }
    for (int i = tid; i < 100 * 256; i += THREADS) {
        int k = i >> 8, n = i & 255;
        W4h[k * 264 + n] = __float2half(W4[i]);
    }
    for (int i = tid; i < 112; i += THREADS) {
        B1f[i] = (i < 100) ? b1[i] : 0.0f;
        B2f[i] = (i < 100) ? b2[i] : 0.0f;
        B3f[i] = (i < 100) ? b3[i] : 0.0f;
    }
    for (int i = tid; i < 256; i += THREADS) B4f[i] = b4[i];
    __syncthreads();

    static const int nt0s[4]  = {0, 4, 8, 11};
    static const int ntcs[4]  = {4, 4, 3, 3};
    const int nt0 = nt0s[q], ntc = ntcs[q];

    for (int t = blockIdx.x; t < NT_TILES; t += GRID) {
        const int base = t * M_TILE;
        if (tid < M_TILE) {
            SRCi[tid] = ei[base + tid];
            DSTi[tid] = ei[N_EDGES + base + tid];
        }
        for (int i = tid; i < M_TILE * 16; i += THREADS) {
            int e = i >> 4, k = i & 15;
            A0h[e * 24 + k] = (k < 8) ? __float2half(ea[(base + e) * 8 + k]) : __half(0.0f);
        }
        for (int i = tid; i < M_TILE * 17; i += THREADS) MSG[i] = 0.0f;
        __syncthreads();

        // gather x[src]: one float4 per thread, scalar stores into padded XV
        {
            int e = tid >> 2, c4 = tid & 3;
            float4 v = ((const float4*)x)[SRCi[e] * 4 + c4];
            float* xr = &XV[e * 17 + c4 * 4];
            xr[0] = v.x; xr[1] = v.y; xr[2] = v.z; xr[3] = v.w;
        }

        layer_f16<1, 4>(A0h, 24,  W1h, 120, B1f, H1h, 120, nt0, ntc, mbase, lane);
        __syncthreads();
        layer_f16<7, 4>(H1h, 120, W2h, 120, B2f, H2h, 120, nt0, ntc, mbase, lane);
        __syncthreads();
        layer_f16<7, 4>(H2h, 120, W3h, 120, B3f, H1h, 120, nt0, ntc, mbase, lane);
        __syncthreads();
        layer4_f16(H1h, W4h, B4f, XV, MSG, q, mbase, lane);
        __syncthreads();

        for (int i = tid; i < M_TILE * 16; i += THREADS) {
            int e = i >> 4, o = i & 15;
            atomicAdd(&g_agg[(long)DSTi[e] * OUT_CH + o], MSG[e * 17 + o]);
        }
        if (tid < M_TILE) atomicAdd(&g_cnt[DSTi[tid]], 1.0f);
        __syncthreads();
    }
}

__global__ void finalize_kernel(const float* __restrict__ x,
                                const float* __restrict__ root,
                                const float* __restrict__ bias,
                                float* __restrict__ out)
{
    int i = blockIdx.x * blockDim.x + threadIdx.x;
    if (i >= N_NODES * OUT_CH) return;
    int n = i >> 4, o = i & 15;
    float c = fmaxf(g_cnt[n], 1.0f);
    float acc = g_agg[i] / c + bias[o];
    const float* xr = x + (long)n * IN_CH;
    #pragma unroll
    for (int k = 0; k < IN_CH; k++)
        acc += xr[k] * root[k * OUT_CH + o];
    out[i] = acc;
}

extern "C" void kernel_launch(void* const* d_in, const int* in_sizes, int n_in,
                              void* d_out, int out_size) {
    const float* x    = (const float*)d_in[0];
    const int*   ei   = (const int*)d_in[1];
    const float* ea   = (const float*)d_in[2];
    const float* W1   = (const float*)d_in[3];
    const float* b1   = (const float*)d_in[4];
    const float* W2   = (const float*)d_in[5];
    const float* b2   = (const float*)d_in[6];
    const float* W3   = (const float*)d_in[7];
    const float* b3   = (const float*)d_in[8];
    const float* W4   = (const float*)d_in[9];
    const float* b4   = (const float*)d_in[10];
    const float* root = (const float*)d_in[11];
    const float* bias = (const float*)d_in[12];
    float* out = (float*)d_out;

    cudaFuncSetAttribute(edge_kernel, cudaFuncAttributeMaxDynamicSharedMemorySize, SMEM_BYTES);

    zero_kernel<<<1024, 256>>>();
    edge_kernel<<<GRID, THREADS, SMEM_BYTES>>>(x, ei, ea, W1, b1, W2, b2, W3, b3, W4, b4);
    finalize_kernel<<<(N_NODES * OUT_CH + 255) / 256, 256>>>(x, root, bias, out);
}

// round 8
// speedup vs baseline: 1.2370x; 1.2370x over previous
#include <cuda_runtime.h>
#include <cuda_fp16.h>
#include <cstdint>

#define N_NODES 50000
#define N_EDGES 800000
#define IN_CH 16
#define OUT_CH 16
#define M_TILE 64
#define NT_TILES (N_EDGES / M_TILE)   // 12500
#define THREADS 256
#define GRID 152

// ---- smem byte offsets ----
#define SM_W1   0        // [16][120] f16   = 3840
#define SM_W2   3840     // [112][120] f16  = 26880
#define SM_W3   30720    // [112][120] f16  = 26880
#define SM_W4   57600    // [112][264] f16  = 59136
#define SM_A0   116736   // [64][24] f16    = 3072
#define SM_H1   119808   // [64][120] f16   = 15360
#define SM_H2   135168   // [64][120] f16   = 15360
#define SM_XV   150528   // [64][17] f32    = 4352
#define SM_MSG  154880   // [64][17] f32    = 4352
#define SM_B1   159232   // [112] f32
#define SM_B2   159680
#define SM_B3   160128
#define SM_B4   160576   // [256] f32
#define SM_IDX  161600   // dst [64] int
#define SM_SRC  161856   // src [64] int
#define SMEM_BYTES 162112
#define W_ZERO_U32 (116736 / 4)

__device__ float g_agg[N_NODES * OUT_CH];
__device__ float g_cnt[N_NODES];

__device__ __forceinline__ uint32_t smem_u32(const void* p) {
    uint32_t a;
    asm("{ .reg .u64 t; cvta.to.shared.u64 t, %1; cvt.u32.u64 %0, t; }" : "=r"(a) : "l"(p));
    return a;
}
__device__ __forceinline__ void group_bar(int id) {
    asm volatile("bar.sync %0, 128;" :: "r"(id) : "memory");
}

#define LDSM_X4(r, a) \
    asm volatile("ldmatrix.sync.aligned.m8n8.x4.shared.b16 {%0,%1,%2,%3}, [%4];" \
        : "=r"((r)[0]), "=r"((r)[1]), "=r"((r)[2]), "=r"((r)[3]) : "r"(a))
#define LDSM_X2T(r, a) \
    asm volatile("ldmatrix.sync.aligned.m8n8.x2.trans.shared.b16 {%0,%1}, [%2];" \
        : "=r"((r)[0]), "=r"((r)[1]) : "r"(a))
#define MMA16816(c, a, b) \
    asm volatile("mma.sync.aligned.m16n8k16.row.col.f32.f16.f16.f32 " \
        "{%0,%1,%2,%3},{%4,%5,%6,%7},{%8,%9},{%0,%1,%2,%3};" \
        : "+f"((c)[0]), "+f"((c)[1]), "+f"((c)[2]), "+f"((c)[3]) \
        : "r"((a)[0]), "r"((a)[1]), "r"((a)[2]), "r"((a)[3]), "r"((b)[0]), "r"((b)[1]))

__global__ void zero_kernel() {
    int total = N_NODES * OUT_CH;
    for (int i = blockIdx.x * blockDim.x + threadIdx.x; i < total; i += gridDim.x * blockDim.x) {
        g_agg[i] = 0.0f;
        if (i < N_NODES) g_cnt[i] = 0.0f;
    }
}

// Generic MLP layer: Hout = relu(Hin @ W + b), fp16 in/out, f32 accum.
// Each warp: 32 rows (its group's m-block), a quarter of the n-columns.
template<int KSTEPS, int MAXNT>
__device__ __forceinline__ void layer_f16(
    const __half* __restrict__ Hin, int sIn,
    const __half* __restrict__ W, int sW,
    const float* __restrict__ bias,
    __half* __restrict__ Hout, int sOut,
    int nt0, int ntCnt, int mbase, int lane)
{
    const int grp = lane >> 2, tig = lane & 3;
    float acc[MAXNT][2][4];
    #pragma unroll
    for (int nt = 0; nt < MAXNT; nt++) {
        if (nt >= ntCnt) break;
        const int c = (nt0 + nt) * 8 + 2 * tig;
        const float b0 = bias[c], b1 = bias[c + 1];
        #pragma unroll
        for (int mt = 0; mt < 2; mt++) {
            acc[nt][mt][0] = b0; acc[nt][mt][1] = b1;
            acc[nt][mt][2] = b0; acc[nt][mt][3] = b1;
        }
    }
    const int arow = mbase + ((lane >> 3) & 1) * 8 + (lane & 7);
    const int acol = (lane >> 4) * 8;
    const int brow = lane & 15;
    #pragma unroll
    for (int k = 0; k < KSTEPS; k++) {
        const int k0 = k * 16;
        uint32_t a[2][4];
        #pragma unroll
        for (int mt = 0; mt < 2; mt++) {
            uint32_t aaddr = smem_u32(Hin + (arow + mt * 16) * sIn + k0 + acol);
            LDSM_X4(a[mt], aaddr);
        }
        #pragma unroll
        for (int nt = 0; nt < MAXNT; nt++) {
            if (nt >= ntCnt) break;
            const int n0 = (nt0 + nt) * 8;
            uint32_t b[2];
            uint32_t baddr = smem_u32(W + (k0 + brow) * sW + n0);
            LDSM_X2T(b, baddr);
            MMA16816(acc[nt][0], a[0], b);
            MMA16816(acc[nt][1], a[1], b);
        }
    }
    #pragma unroll
    for (int nt = 0; nt < MAXNT; nt++) {
        if (nt >= ntCnt) break;
        const int n0 = (nt0 + nt) * 8;
        #pragma unroll
        for (int mt = 0; mt < 2; mt++) {
            const int r0 = mbase + mt * 16 + grp;
            __half2 v0 = __floats2half2_rn(fmaxf(acc[nt][mt][0], 0.f), fmaxf(acc[nt][mt][1], 0.f));
            __half2 v1 = __floats2half2_rn(fmaxf(acc[nt][mt][2], 0.f), fmaxf(acc[nt][mt][3], 0.f));
            *(__half2*)(Hout + r0 * sOut + n0 + 2 * tig) = v0;
            *(__half2*)(Hout + (r0 + 8) * sOut + n0 + 2 * tig) = v1;
        }
    }
}

// Layer 4 (100->256, no relu) with fused einsum epilogue into MSG (smem atomics).
__device__ __forceinline__ void layer4_f16(
    const __half* __restrict__ Hin,
    const __half* __restrict__ W4h,
    const float* __restrict__ b4f,
    const float* __restrict__ XV,
    float* __restrict__ MSG,
    int q, int mbase, int lane)
{
    const int grp = lane >> 2, tig = lane & 3;
    float acc[8][2][4];
    #pragma unroll
    for (int nt = 0; nt < 8; nt++) {
        const int c = (q * 8 + nt) * 8 + 2 * tig;
        const float b0 = b4f[c], b1 = b4f[c + 1];
        #pragma unroll
        for (int mt = 0; mt < 2; mt++) {
            acc[nt][mt][0] = b0; acc[nt][mt][1] = b1;
            acc[nt][mt][2] = b0; acc[nt][mt][3] = b1;
        }
    }
    const int arow = mbase + ((lane >> 3) & 1) * 8 + (lane & 7);
    const int acol = (lane >> 4) * 8;
    const int brow = lane & 15;
    #pragma unroll
    for (int k = 0; k < 7; k++) {
        const int k0 = k * 16;
        uint32_t a[2][4];
        #pragma unroll
        for (int mt = 0; mt < 2; mt++) {
            uint32_t aaddr = smem_u32(Hin + (arow + mt * 16) * 120 + k0 + acol);
            LDSM_X4(a[mt], aaddr);
        }
        #pragma unroll
        for (int nt = 0; nt < 8; nt++) {
            const int n0 = (q * 8 + nt) * 8;
            uint32_t b[2];
            uint32_t baddr = smem_u32(W4h + (k0 + brow) * 264 + n0);
            LDSM_X2T(b, baddr);
            MMA16816(acc[nt][0], a[0], b);
            MMA16816(acc[nt][1], a[1], b);
        }
    }
    #pragma unroll
    for (int nt = 0; nt < 8; nt++) {
        const int c = (q * 8 + nt) * 8 + 2 * tig;   // even
        const int i = c >> 4, o = c & 15;
        #pragma unroll
        for (int mt = 0; mt < 2; mt++) {
            const int e0 = mbase + mt * 16 + grp, e1 = e0 + 8;
            const float xv0 = XV[e0 * 17 + i], xv1 = XV[e1 * 17 + i];
            atomicAdd(&MSG[e0 * 17 + o],     xv0 * acc[nt][mt][0]);
            atomicAdd(&MSG[e0 * 17 + o + 1], xv0 * acc[nt][mt][1]);
            atomicAdd(&MSG[e1 * 17 + o],     xv1 * acc[nt][mt][2]);
            atomicAdd(&MSG[e1 * 17 + o + 1], xv1 * acc[nt][mt][3]);
        }
    }
}

extern __shared__ char smem[];

__global__ void __launch_bounds__(THREADS, 1)
edge_kernel(const float* __restrict__ x,
            const int* __restrict__ ei,
            const float* __restrict__ ea,
            const float* __restrict__ W1, const float* __restrict__ b1,
            const float* __restrict__ W2, const float* __restrict__ b2,
            const float* __restrict__ W3, const float* __restrict__ b3,
            const float* __restrict__ W4, const float* __restrict__ b4)
{
    const int tid = threadIdx.x;
    const int wid = tid >> 5, lane = tid & 31;
    const int q = wid & 3;
    const int g = wid >> 2;            // group 0/1 (independent after init)
    const int mbase = g * 32;
    const int tidg = tid & 127;        // tid within group
    const int barid = g + 1;

    __half* W1h = (__half*)(smem + SM_W1);
    __half* W2h = (__half*)(smem + SM_W2);
    __half* W3h = (__half*)(smem + SM_W3);
    __half* W4h = (__half*)(smem + SM_W4);
    __half* A0h = (__half*)(smem + SM_A0);
    __half* H1h = (__half*)(smem + SM_H1);
    __half* H2h = (__half*)(smem + SM_H2);
    float*  XV  = (float*)(smem + SM_XV);
    float*  MSG = (float*)(smem + SM_MSG);
    float*  B1f = (float*)(smem + SM_B1);
    float*  B2f = (float*)(smem + SM_B2);
    float*  B3f = (float*)(smem + SM_B3);
    float*  B4f = (float*)(smem + SM_B4);
    int*    DSTi = (int*)(smem + SM_IDX);
    int*    SRCi = (int*)(smem + SM_SRC);

    // zero weight region (covers K/N zero-padding)
    for (int i = tid; i < W_ZERO_U32; i += THREADS) ((uint32_t*)smem)[i] = 0;
    __syncthreads();
    for (int i = tid; i < 8 * 100; i += THREADS) {
        int k = i / 100, n = i % 100;
        W1h[k * 120 + n] = __float2half(W1[i]);
    }
    for (int i = tid; i < 100 * 100; i += THREADS) {
        int k = i / 100, n = i % 100;
        W2h[k * 120 + n] = __float2half(W2[i]);
        W3h[k * 120 + n] = __float2half(W3[i]);
    }
    for (int i = tid; i < 100 * 256; i += THREADS) {
        int k = i >> 8, n = i & 255;
        W4h[k * 264 + n] = __float2half(W4[i]);
    }
    for (int i = tid; i < 112; i += THREADS) {
        B1f[i] = (i < 100) ? b1[i] : 0.0f;
        B2f[i] = (i < 100) ? b2[i] : 0.0f;
        B3f[i] = (i < 100) ? b3[i] : 0.0f;
    }
    for (int i = tid; i < 256; i += THREADS) B4f[i] = b4[i];
    __syncthreads();

    static const int nt0s[4]  = {0, 4, 8, 11};
    static const int ntcs[4]  = {4, 4, 3, 3};
    const int nt0 = nt0s[q], ntc = ntcs[q];

    // Each 128-thread group owns rows [mbase, mbase+32) of every staging buffer.
    // Groups never interact inside the loop: group-local named barriers only.
    for (int t = blockIdx.x; t < NT_TILES; t += GRID) {
        const int base = t * M_TILE + mbase;   // this group's 32 edges
        if (tidg < 32) {
            SRCi[mbase + tidg] = ei[base + tidg];
            DSTi[mbase + tidg] = ei[N_EDGES + base + tidg];
        }
        // A0: 32 edges x 16 cols fp16 (8 real, 8 zero-pad)
        for (int i = tidg; i < 32 * 16; i += 128) {
            int e = i >> 4, k = i & 15;
            A0h[(mbase + e) * 24 + k] = (k < 8) ? __float2half(ea[(base + e) * 8 + k]) : __half(0.0f);
        }
        // MSG zero: 32 rows x 17
        for (int i = tidg; i < 32 * 17; i += 128) MSG[mbase * 17 + i] = 0.0f;
        group_bar(barid);

        // gather x[src]: one float4 per thread (32 edges x 4 float4)
        {
            int e = tidg >> 2, c4 = tidg & 3;
            float4 v = ((const float4*)x)[SRCi[mbase + e] * 4 + c4];
            float* xr = &XV[(mbase + e) * 17 + c4 * 4];
            xr[0] = v.x; xr[1] = v.y; xr[2] = v.z; xr[3] = v.w;
        }

        layer_f16<1, 4>(A0h, 24,  W1h, 120, B1f, H1h, 120, nt0, ntc, mbase, lane);
        group_bar(barid);
        layer_f16<7, 4>(H1h, 120, W2h, 120, B2f, H2h, 120, nt0, ntc, mbase, lane);
        group_bar(barid);
        layer_f16<7, 4>(H2h, 120, W3h, 120, B3f, H1h, 120, nt0, ntc, mbase, lane);
        group_bar(barid);
        layer4_f16(H1h, W4h, B4f, XV, MSG, q, mbase, lane);
        group_bar(barid);

        // scatter this group's 32 edges
        for (int i = tidg; i < 32 * 16; i += 128) {
            int e = mbase + (i >> 4), o = i & 15;
            atomicAdd(&g_agg[(long)DSTi[e] * OUT_CH + o], MSG[e * 17 + o]);
        }
        if (tidg < 32) atomicAdd(&g_cnt[DSTi[mbase + tidg]], 1.0f);
        group_bar(barid);
    }
}

__global__ void finalize_kernel(const float* __restrict__ x,
                                const float* __restrict__ root,
                                const float* __restrict__ bias,
                                float* __restrict__ out)
{
    int i = blockIdx.x * blockDim.x + threadIdx.x;
    if (i >= N_NODES * OUT_CH) return;
    int n = i >> 4, o = i & 15;
    float c = fmaxf(g_cnt[n], 1.0f);
    float acc = g_agg[i] / c + bias[o];
    const float* xr = x + (long)n * IN_CH;
    #pragma unroll
    for (int k = 0; k < IN_CH; k++)
        acc += xr[k] * root[k * OUT_CH + o];
    out[i] = acc;
}

extern "C" void kernel_launch(void* const* d_in, const int* in_sizes, int n_in,
                              void* d_out, int out_size) {
    const float* x    = (const float*)d_in[0];
    const int*   ei   = (const int*)d_in[1];
    const float* ea   = (const float*)d_in[2];
    const float* W1   = (const float*)d_in[3];
    const float* b1   = (const float*)d_in[4];
    const float* W2   = (const float*)d_in[5];
    const float* b2   = (const float*)d_in[6];
    const float* W3   = (const float*)d_in[7];
    const float* b3   = (const float*)d_in[8];
    const float* W4   = (const float*)d_in[9];
    const float* b4   = (const float*)d_in[10];
    const float* root = (const float*)d_in[11];
    const float* bias = (const float*)d_in[12];
    float* out = (float*)d_out;

    cudaFuncSetAttribute(edge_kernel, cudaFuncAttributeMaxDynamicSharedMemorySize, SMEM_BYTES);

    zero_kernel<<<1024, 256>>>();
    edge_kernel<<<GRID, THREADS, SMEM_BYTES>>>(x, ei, ea, W1, b1, W2, b2, W3, b3, W4, b4);
    finalize_kernel<<<(N_NODES * OUT_CH + 255) / 256, 256>>>(x, root, bias, out);
}

// round 9
// speedup vs baseline: 1.7700x; 1.4309x over previous
#include <cuda_runtime.h>
#include <cuda_fp16.h>
#include <cstdint>

#define N_NODES 50000
#define N_EDGES 800000
#define IN_CH 16
#define OUT_CH 16
#define M_TILE 64
#define NT_TILES (N_EDGES / M_TILE)   // 12500
#define THREADS 256
#define GRID 152

// ---- smem byte offsets ----
#define SM_W1   0        // [16][120] f16   = 3840
#define SM_W2   3840     // [112][120] f16  = 26880
#define SM_W3   30720    // [112][120] f16  = 26880
#define SM_W4   57600    // [112][264] f16  = 59136
#define SM_A0   116736   // [64][24] f16    = 3072
#define SM_H1   119808   // [64][120] f16   = 15360
#define SM_H2   135168   // [64][120] f16   = 15360
#define SM_XV   150528   // [64][17] f32    = 4352
#define SM_MSGP 154880   // [2][4][32][18] f32 = 18432 (per-warp partials)
#define SM_B1   173312   // [112] f32
#define SM_B2   173760
#define SM_B3   174208
#define SM_B4   174656   // [256] f32
#define SM_IDX  175680   // dst [64] int
#define SM_SRC  175936   // src [64] int
#define SMEM_BYTES 176192
#define W_ZERO_U32 (116736 / 4)

__device__ float g_agg[N_NODES * OUT_CH];
__device__ float g_cnt[N_NODES];

__device__ __forceinline__ uint32_t smem_u32(const void* p) {
    uint32_t a;
    asm("{ .reg .u64 t; cvta.to.shared.u64 t, %1; cvt.u32.u64 %0, t; }" : "=r"(a) : "l"(p));
    return a;
}
__device__ __forceinline__ void group_bar(int id) {
    asm volatile("bar.sync %0, 128;" :: "r"(id) : "memory");
}

#define LDSM_X4(r, a) \
    asm volatile("ldmatrix.sync.aligned.m8n8.x4.shared.b16 {%0,%1,%2,%3}, [%4];" \
        : "=r"((r)[0]), "=r"((r)[1]), "=r"((r)[2]), "=r"((r)[3]) : "r"(a))
#define LDSM_X2(r, a) \
    asm volatile("ldmatrix.sync.aligned.m8n8.x2.shared.b16 {%0,%1}, [%2];" \
        : "=r"((r)[0]), "=r"((r)[1]) : "r"(a))
#define LDSM_X2T(r, a) \
    asm volatile("ldmatrix.sync.aligned.m8n8.x2.trans.shared.b16 {%0,%1}, [%2];" \
        : "=r"((r)[0]), "=r"((r)[1]) : "r"(a))
#define LDSM_X1T(r, a) \
    asm volatile("ldmatrix.sync.aligned.m8n8.x1.trans.shared.b16 {%0}, [%1];" \
        : "=r"(r) : "r"(a))
#define MMA16816(c, a, b) \
    asm volatile("mma.sync.aligned.m16n8k16.row.col.f32.f16.f16.f32 " \
        "{%0,%1,%2,%3},{%4,%5,%6,%7},{%8,%9},{%0,%1,%2,%3};" \
        : "+f"((c)[0]), "+f"((c)[1]), "+f"((c)[2]), "+f"((c)[3]) \
        : "r"((a)[0]), "r"((a)[1]), "r"((a)[2]), "r"((a)[3]), "r"((b)[0]), "r"((b)[1]))
#define MMA1688(c, a, b) \
    asm volatile("mma.sync.aligned.m16n8k8.row.col.f32.f16.f16.f32 " \
        "{%0,%1,%2,%3},{%4,%5},{%6},{%0,%1,%2,%3};" \
        : "+f"((c)[0]), "+f"((c)[1]), "+f"((c)[2]), "+f"((c)[3]) \
        : "r"((a)[0]), "r"((a)[1]), "r"(b))

__global__ void zero_kernel() {
    int total = N_NODES * OUT_CH;
    for (int i = blockIdx.x * blockDim.x + threadIdx.x; i < total; i += gridDim.x * blockDim.x) {
        g_agg[i] = 0.0f;
        if (i < N_NODES) g_cnt[i] = 0.0f;
    }
}

// MLP layer: Hout = relu(Hin @ W + b). K = K16*16 (+8 if TAIL).
template<int K16, int MAXNT, bool TAIL>
__device__ __forceinline__ void layer_f16(
    const __half* __restrict__ Hin, int sIn,
    const __half* __restrict__ W, int sW,
    const float* __restrict__ bias,
    __half* __restrict__ Hout, int sOut,
    int nt0, int ntCnt, int mbase, int lane)
{
    const int grp = lane >> 2, tig = lane & 3;
    float acc[MAXNT][2][4];
    #pragma unroll
    for (int nt = 0; nt < MAXNT; nt++) {
        if (nt >= ntCnt) break;
        const int c = (nt0 + nt) * 8 + 2 * tig;
        const float b0 = bias[c], b1 = bias[c + 1];
        #pragma unroll
        for (int mt = 0; mt < 2; mt++) {
            acc[nt][mt][0] = b0; acc[nt][mt][1] = b1;
            acc[nt][mt][2] = b0; acc[nt][mt][3] = b1;
        }
    }
    const int arow = mbase + ((lane >> 3) & 1) * 8 + (lane & 7);
    const int acol = (lane >> 4) * 8;
    const int brow = lane & 15;
    #pragma unroll
    for (int k = 0; k < K16; k++) {
        const int k0 = k * 16;
        uint32_t a[2][4];
        #pragma unroll
        for (int mt = 0; mt < 2; mt++) {
            uint32_t aaddr = smem_u32(Hin + (arow + mt * 16) * sIn + k0 + acol);
            LDSM_X4(a[mt], aaddr);
        }
        #pragma unroll
        for (int nt = 0; nt < MAXNT; nt++) {
            if (nt >= ntCnt) break;
            const int n0 = (nt0 + nt) * 8;
            uint32_t b[2];
            uint32_t baddr = smem_u32(W + (k0 + brow) * sW + n0);
            LDSM_X2T(b, baddr);
            MMA16816(acc[nt][0], a[0], b);
            MMA16816(acc[nt][1], a[1], b);
        }
    }
    if (TAIL) {  // k8 step covering k = 96..103 (zero-padded beyond 100)
        const int k0 = K16 * 16;
        uint32_t a2[2][2];
        #pragma unroll
        for (int mt = 0; mt < 2; mt++) {
            uint32_t aaddr = smem_u32(Hin + (arow + mt * 16) * sIn + k0);
            LDSM_X2(a2[mt], aaddr);
        }
        #pragma unroll
        for (int nt = 0; nt < MAXNT; nt++) {
            if (nt >= ntCnt) break;
            const int n0 = (nt0 + nt) * 8;
            uint32_t b0;
            uint32_t baddr = smem_u32(W + (k0 + (lane & 7)) * sW + n0);
            LDSM_X1T(b0, baddr);
            MMA1688(acc[nt][0], a2[0], b0);
            MMA1688(acc[nt][1], a2[1], b0);
        }
    }
    #pragma unroll
    for (int nt = 0; nt < MAXNT; nt++) {
        if (nt >= ntCnt) break;
        const int n0 = (nt0 + nt) * 8;
        #pragma unroll
        for (int mt = 0; mt < 2; mt++) {
            const int r0 = mbase + mt * 16 + grp;
            __half2 v0 = __floats2half2_rn(fmaxf(acc[nt][mt][0], 0.f), fmaxf(acc[nt][mt][1], 0.f));
            __half2 v1 = __floats2half2_rn(fmaxf(acc[nt][mt][2], 0.f), fmaxf(acc[nt][mt][3], 0.f));
            *(__half2*)(Hout + r0 * sOut + n0 + 2 * tig) = v0;
            *(__half2*)(Hout + (r0 + 8) * sOut + n0 + 2 * tig) = v1;
        }
    }
}

// Layer 4 (100->256, no relu): fused einsum accumulated in registers,
// written as conflict-free float2 stores into this warp's MSGP partial buffer.
__device__ __forceinline__ void layer4_f16(
    const __half* __restrict__ Hin,
    const __half* __restrict__ W4h,
    const float* __restrict__ b4f,
    const float* __restrict__ XV,
    float* __restrict__ msgp,     // this warp's [32][18] partial buffer
    int q, int mbase, int lane)
{
    const int grp = lane >> 2, tig = lane & 3;
    float acc[8][2][4];
    #pragma unroll
    for (int nt = 0; nt < 8; nt++) {
        const int c = (q * 8 + nt) * 8 + 2 * tig;
        const float b0 = b4f[c], b1 = b4f[c + 1];
        #pragma unroll
        for (int mt = 0; mt < 2; mt++) {
            acc[nt][mt][0] = b0; acc[nt][mt][1] = b1;
            acc[nt][mt][2] = b0; acc[nt][mt][3] = b1;
        }
    }
    const int arow = mbase + ((lane >> 3) & 1) * 8 + (lane & 7);
    const int acol = (lane >> 4) * 8;
    const int brow = lane & 15;
    #pragma unroll
    for (int k = 0; k < 6; k++) {
        const int k0 = k * 16;
        uint32_t a[2][4];
        #pragma unroll
        for (int mt = 0; mt < 2; mt++) {
            uint32_t aaddr = smem_u32(Hin + (arow + mt * 16) * 120 + k0 + acol);
            LDSM_X4(a[mt], aaddr);
        }
        #pragma unroll
        for (int nt = 0; nt < 8; nt++) {
            const int n0 = (q * 8 + nt) * 8;
            uint32_t b[2];
            uint32_t baddr = smem_u32(W4h + (k0 + brow) * 264 + n0);
            LDSM_X2T(b, baddr);
            MMA16816(acc[nt][0], a[0], b);
            MMA16816(acc[nt][1], a[1], b);
        }
    }
    {   // k8 tail, k = 96..103
        const int k0 = 96;
        uint32_t a2[2][2];
        #pragma unroll
        for (int mt = 0; mt < 2; mt++) {
            uint32_t aaddr = smem_u32(Hin + (arow + mt * 16) * 120 + k0);
            LDSM_X2(a2[mt], aaddr);
        }
        #pragma unroll
        for (int nt = 0; nt < 8; nt++) {
            const int n0 = (q * 8 + nt) * 8;
            uint32_t b0;
            uint32_t baddr = smem_u32(W4h + (k0 + (lane & 7)) * 264 + n0);
            LDSM_X1T(b0, baddr);
            MMA1688(acc[nt][0], a2[0], b0);
            MMA1688(acc[nt][1], a2[1], b0);
        }
    }

    // hoisted XV loads: 4 edges x 4 i-values (broadcast across tig lanes)
    float xvr[4][4];
    #pragma unroll
    for (int mt = 0; mt < 2; mt++)
        #pragma unroll
        for (int h = 0; h < 2; h++) {
            const int e = mbase + mt * 16 + grp + 8 * h;
            #pragma unroll
            for (int ii = 0; ii < 4; ii++)
                xvr[mt * 2 + h][ii] = XV[e * 17 + 4 * q + ii];
        }

    // accumulate einsum: msgacc[edge-slot 4][o-parity 2][pair 2]
    float msgacc[4][2][2];
    #pragma unroll
    for (int s = 0; s < 4; s++)
        #pragma unroll
        for (int p = 0; p < 2; p++) { msgacc[s][p][0] = 0.f; msgacc[s][p][1] = 0.f; }
    #pragma unroll
    for (int nt = 0; nt < 8; nt++) {
        const int par = nt & 1;          // o-pair parity: o = 2tig (+8 if odd)
        const int ii = nt >> 1;          // i = 4q + ii
        #pragma unroll
        for (int mt = 0; mt < 2; mt++) {
            const float xv0 = xvr[mt * 2 + 0][ii];
            const float xv1 = xvr[mt * 2 + 1][ii];
            msgacc[mt * 2 + 0][par][0] += xv0 * acc[nt][mt][0];
            msgacc[mt * 2 + 0][par][1] += xv0 * acc[nt][mt][1];
            msgacc[mt * 2 + 1][par][0] += xv1 * acc[nt][mt][2];
            msgacc[mt * 2 + 1][par][1] += xv1 * acc[nt][mt][3];
        }
    }
    // store partials: e_loc = mt*16 + grp + 8h, o = 2tig + 8par (float2, stride 18)
    #pragma unroll
    for (int mt = 0; mt < 2; mt++)
        #pragma unroll
        for (int h = 0; h < 2; h++) {
            const int e_loc = mt * 16 + grp + 8 * h;
            #pragma unroll
            for (int par = 0; par < 2; par++) {
                float2 v = make_float2(msgacc[mt * 2 + h][par][0], msgacc[mt * 2 + h][par][1]);
                *(float2*)&msgp[e_loc * 18 + 2 * tig + 8 * par] = v;
            }
        }
}

extern __shared__ char smem[];

__global__ void __launch_bounds__(THREADS, 1)
edge_kernel(const float* __restrict__ x,
            const int* __restrict__ ei,
            const float* __restrict__ ea,
            const float* __restrict__ W1, const float* __restrict__ b1,
            const float* __restrict__ W2, const float* __restrict__ b2,
            const float* __restrict__ W3, const float* __restrict__ b3,
            const float* __restrict__ W4, const float* __restrict__ b4)
{
    const int tid = threadIdx.x;
    const int wid = tid >> 5, lane = tid & 31;
    const int q = wid & 3;
    const int g = wid >> 2;            // group 0/1 (independent after init)
    const int mbase = g * 32;
    const int tidg = tid & 127;
    const int barid = g + 1;

    __half* W1h = (__half*)(smem + SM_W1);
    __half* W2h = (__half*)(smem + SM_W2);
    __half* W3h = (__half*)(smem + SM_W3);
    __half* W4h = (__half*)(smem + SM_W4);
    __half* A0h = (__half*)(smem + SM_A0);
    __half* H1h = (__half*)(smem + SM_H1);
    __half* H2h = (__half*)(smem + SM_H2);
    float*  XV  = (float*)(smem + SM_XV);
    float*  MSGP = (float*)(smem + SM_MSGP);
    float*  B1f = (float*)(smem + SM_B1);
    float*  B2f = (float*)(smem + SM_B2);
    float*  B3f = (float*)(smem + SM_B3);
    float*  B4f = (float*)(smem + SM_B4);
    int*    DSTi = (int*)(smem + SM_IDX);
    int*    SRCi = (int*)(smem + SM_SRC);

    for (int i = tid; i < W_ZERO_U32; i += THREADS) ((uint32_t*)smem)[i] = 0;
    __syncthreads();
    for (int i = tid; i < 8 * 100; i += THREADS) {
        int k = i / 100, n = i % 100;
        W1h[k * 120 + n] = __float2half(W1[i]);
    }
    for (int i = tid; i < 100 * 100; i += THREADS) {
        int k = i / 100, n = i % 100;
        W2h[k * 120 + n] = __float2half(W2[i]);
        W3h[k * 120 + n] = __float2half(W3[i]);
    }
    for (int i = tid; i < 100 * 256; i += THREADS) {
        int k = i >> 8, n = i & 255;
        W4h[k * 264 + n] = __float2half(W4[i]);
    }
    for (int i = tid; i < 112; i += THREADS) {
        B1f[i] = (i < 100) ? b1[i] : 0.0f;
        B2f[i] = (i < 100) ? b2[i] : 0.0f;
        B3f[i] = (i < 100) ? b3[i] : 0.0f;
    }
    for (int i = tid; i < 256; i += THREADS) B4f[i] = b4[i];
    __syncthreads();

    static const int nt0s[4]  = {0, 4, 8, 11};
    static const int ntcs[4]  = {4, 4, 3, 3};
    const int nt0 = nt0s[q], ntc = ntcs[q];
    float* msgp_w = MSGP + (g * 4 + q) * 576;   // this warp's [32][18]
    float* msgp_g = MSGP + g * 4 * 576;         // group base

    for (int t = blockIdx.x; t < NT_TILES; t += GRID) {
        const int base = t * M_TILE + mbase;   // this group's 32 edges
        if (tidg < 32) {
            SRCi[mbase + tidg] = ei[base + tidg];
            DSTi[mbase + tidg] = ei[N_EDGES + base + tidg];
        }
        for (int i = tidg; i < 32 * 16; i += 128) {
            int e = i >> 4, k = i & 15;
            A0h[(mbase + e) * 24 + k] = (k < 8) ? __float2half(ea[(base + e) * 8 + k]) : __half(0.0f);
        }
        group_bar(barid);

        {
            int e = tidg >> 2, c4 = tidg & 3;
            float4 v = ((const float4*)x)[SRCi[mbase + e] * 4 + c4];
            float* xr = &XV[(mbase + e) * 17 + c4 * 4];
            xr[0] = v.x; xr[1] = v.y; xr[2] = v.z; xr[3] = v.w;
        }

        layer_f16<1, 4, false>(A0h, 24,  W1h, 120, B1f, H1h, 120, nt0, ntc, mbase, lane);
        group_bar(barid);
        layer_f16<6, 4, true>(H1h, 120, W2h, 120, B2f, H2h, 120, nt0, ntc, mbase, lane);
        group_bar(barid);
        layer_f16<6, 4, true>(H2h, 120, W3h, 120, B3f, H1h, 120, nt0, ntc, mbase, lane);
        group_bar(barid);
        layer4_f16(H1h, W4h, B4f, XV, msgp_w, q, mbase, lane);
        group_bar(barid);

        // scatter: sum 4 warp partials, one global RED per (e,o)
        for (int i = tidg; i < 32 * 16; i += 128) {
            int e = i >> 4, o = i & 15;
            float s = msgp_g[e * 18 + o] + msgp_g[576 + e * 18 + o]
                    + msgp_g[1152 + e * 18 + o] + msgp_g[1728 + e * 18 + o];
            atomicAdd(&g_agg[(long)DSTi[mbase + e] * OUT_CH + o], s);
        }
        if (tidg < 32) atomicAdd(&g_cnt[DSTi[mbase + tidg]], 1.0f);
        group_bar(barid);
    }
}

__global__ void finalize_kernel(const float* __restrict__ x,
                                const float* __restrict__ root,
                                const float* __restrict__ bias,
                                float* __restrict__ out)
{
    int i = blockIdx.x * blockDim.x + threadIdx.x;
    if (i >= N_NODES * OUT_CH) return;
    int n = i >> 4, o = i & 15;
    float c = fmaxf(g_cnt[n], 1.0f);
    float acc = g_agg[i] / c + bias[o];
    const float* xr = x + (long)n * IN_CH;
    #pragma unroll
    for (int k = 0; k < IN_CH; k++)
        acc += xr[k] * root[k * OUT_CH + o];
    out[i] = acc;
}

extern "C" void kernel_launch(void* const* d_in, const int* in_sizes, int n_in,
                              void* d_out, int out_size) {
    const float* x    = (const float*)d_in[0];
    const int*   ei   = (const int*)d_in[1];
    const float* ea   = (const float*)d_in[2];
    const float* W1   = (const float*)d_in[3];
    const float* b1   = (const float*)d_in[4];
    const float* W2   = (const float*)d_in[5];
    const float* b2   = (const float*)d_in[6];
    const float* W3   = (const float*)d_in[7];
    const float* b3   = (const float*)d_in[8];
    const float* W4   = (const float*)d_in[9];
    const float* b4   = (const float*)d_in[10];
    const float* root = (const float*)d_in[11];
    const float* bias = (const float*)d_in[12];
    float* out = (float*)d_out;

    cudaFuncSetAttribute(edge_kernel, cudaFuncAttributeMaxDynamicSharedMemorySize, SMEM_BYTES);

    zero_kernel<<<1024, 256>>>();
    edge_kernel<<<GRID, THREADS, SMEM_BYTES>>>(x, ei, ea, W1, b1, W2, b2, W3, b3, W4, b4);
    finalize_kernel<<<(N_NODES * OUT_CH + 255) / 256, 256>>>(x, root, bias, out);
}

// round 10
// speedup vs baseline: 2.3270x; 1.3147x over previous
#include <cuda_runtime.h>
#include <cuda_fp16.h>
#include <cstdint>

#define N_NODES 50000
#define N_EDGES 800000
#define IN_CH 16
#define OUT_CH 16
#define M_TILE 64
#define NT_TILES (N_EDGES / M_TILE)   // 12500
#define THREADS 256
#define GRID 152

// ---- smem byte offsets ----
#define SM_W1   0        // [16][120] f16   = 3840
#define SM_W2   3840     // [112][120] f16  = 26880
#define SM_W3   30720    // [112][120] f16  = 26880
#define SM_W4   57600    // [112][264] f16  = 59136
#define SM_A0   116736   // [64][24] f16    = 3072
#define SM_H1   119808   // [64][120] f16   = 15360
#define SM_H2   135168   // [64][120] f16   = 15360
#define SM_XV   150528   // [64][17] f32    = 4352
#define SM_MSGP 154880   // [2][4][32][18] f32 = 18432 (per-warp partials)
#define SM_B1   173312   // [112] f32
#define SM_B2   173760
#define SM_B3   174208
#define SM_B4   174656   // [256] f32
#define SM_IDX  175680   // dst [64] int
#define SM_SRC  175936   // src [64] int
#define SMEM_BYTES 176192
#define W_ZERO_U32 (116736 / 4)

__device__ float g_agg[N_NODES * OUT_CH];
__device__ float g_cnt[N_NODES];

__device__ __forceinline__ uint32_t smem_u32(const void* p) {
    uint32_t a;
    asm("{ .reg .u64 t; cvta.to.shared.u64 t, %1; cvt.u32.u64 %0, t; }" : "=r"(a) : "l"(p));
    return a;
}
__device__ __forceinline__ void group_bar(int id) {
    asm volatile("bar.sync %0, 128;" :: "r"(id) : "memory");
}

#define LDSM_X4(r, a) \
    asm volatile("ldmatrix.sync.aligned.m8n8.x4.shared.b16 {%0,%1,%2,%3}, [%4];" \
        : "=r"((r)[0]), "=r"((r)[1]), "=r"((r)[2]), "=r"((r)[3]) : "r"(a))
#define LDSM_X2(r, a) \
    asm volatile("ldmatrix.sync.aligned.m8n8.x2.shared.b16 {%0,%1}, [%2];" \
        : "=r"((r)[0]), "=r"((r)[1]) : "r"(a))
#define LDSM_X2T(r, a) \
    asm volatile("ldmatrix.sync.aligned.m8n8.x2.trans.shared.b16 {%0,%1}, [%2];" \
        : "=r"((r)[0]), "=r"((r)[1]) : "r"(a))
#define LDSM_X1T(r, a) \
    asm volatile("ldmatrix.sync.aligned.m8n8.x1.trans.shared.b16 {%0}, [%1];" \
        : "=r"(r) : "r"(a))
#define MMA16816(c, a, b) \
    asm volatile("mma.sync.aligned.m16n8k16.row.col.f32.f16.f16.f32 " \
        "{%0,%1,%2,%3},{%4,%5,%6,%7},{%8,%9},{%0,%1,%2,%3};" \
        : "+f"((c)[0]), "+f"((c)[1]), "+f"((c)[2]), "+f"((c)[3]) \
        : "r"((a)[0]), "r"((a)[1]), "r"((a)[2]), "r"((a)[3]), "r"((b)[0]), "r"((b)[1]))
#define MMA1688(c, a, b) \
    asm volatile("mma.sync.aligned.m16n8k8.row.col.f32.f16.f16.f32 " \
        "{%0,%1,%2,%3},{%4,%5},{%6},{%0,%1,%2,%3};" \
        : "+f"((c)[0]), "+f"((c)[1]), "+f"((c)[2]), "+f"((c)[3]) \
        : "r"((a)[0]), "r"((a)[1]), "r"(b))

__global__ void zero_kernel() {
    int total = N_NODES * OUT_CH;
    for (int i = blockIdx.x * blockDim.x + threadIdx.x; i < total; i += gridDim.x * blockDim.x) {
        g_agg[i] = 0.0f;
        if (i < N_NODES) g_cnt[i] = 0.0f;
    }
}

// MLP layer: Hout = relu(Hin @ W + b). K = K16*16 (+8 if TAIL).
template<int K16, int MAXNT, bool TAIL>
__device__ __forceinline__ void layer_f16(
    const __half* __restrict__ Hin, int sIn,
    const __half* __restrict__ W, int sW,
    const float* __restrict__ bias,
    __half* __restrict__ Hout, int sOut,
    int nt0, int ntCnt, int mbase, int lane)
{
    const int grp = lane >> 2, tig = lane & 3;
    float acc[MAXNT][2][4];
    #pragma unroll
    for (int nt = 0; nt < MAXNT; nt++) {
        if (nt >= ntCnt) break;
        const int c = (nt0 + nt) * 8 + 2 * tig;
        const float b0 = bias[c], b1 = bias[c + 1];
        #pragma unroll
        for (int mt = 0; mt < 2; mt++) {
            acc[nt][mt][0] = b0; acc[nt][mt][1] = b1;
            acc[nt][mt][2] = b0; acc[nt][mt][3] = b1;
        }
    }
    const int arow = mbase + ((lane >> 3) & 1) * 8 + (lane & 7);
    const int acol = (lane >> 4) * 8;
    const int brow = lane & 15;
    #pragma unroll
    for (int k = 0; k < K16; k++) {
        const int k0 = k * 16;
        uint32_t a[2][4];
        #pragma unroll
        for (int mt = 0; mt < 2; mt++) {
            uint32_t aaddr = smem_u32(Hin + (arow + mt * 16) * sIn + k0 + acol);
            LDSM_X4(a[mt], aaddr);
        }
        #pragma unroll
        for (int nt = 0; nt < MAXNT; nt++) {
            if (nt >= ntCnt) break;
            const int n0 = (nt0 + nt) * 8;
            uint32_t b[2];
            uint32_t baddr = smem_u32(W + (k0 + brow) * sW + n0);
            LDSM_X2T(b, baddr);
            MMA16816(acc[nt][0], a[0], b);
            MMA16816(acc[nt][1], a[1], b);
        }
    }
    if (TAIL) {  // k8 step at k0 = K16*16 (zero-padded where needed)
        const int k0 = K16 * 16;
        uint32_t a2[2][2];
        #pragma unroll
        for (int mt = 0; mt < 2; mt++) {
            uint32_t aaddr = smem_u32(Hin + (arow + mt * 16) * sIn + k0);
            LDSM_X2(a2[mt], aaddr);
        }
        #pragma unroll
        for (int nt = 0; nt < MAXNT; nt++) {
            if (nt >= ntCnt) break;
            const int n0 = (nt0 + nt) * 8;
            uint32_t b0;
            uint32_t baddr = smem_u32(W + (k0 + (lane & 7)) * sW + n0);
            LDSM_X1T(b0, baddr);
            MMA1688(acc[nt][0], a2[0], b0);
            MMA1688(acc[nt][1], a2[1], b0);
        }
    }
    #pragma unroll
    for (int nt = 0; nt < MAXNT; nt++) {
        if (nt >= ntCnt) break;
        const int n0 = (nt0 + nt) * 8;
        #pragma unroll
        for (int mt = 0; mt < 2; mt++) {
            const int r0 = mbase + mt * 16 + grp;
            __half2 v0 = __floats2half2_rn(fmaxf(acc[nt][mt][0], 0.f), fmaxf(acc[nt][mt][1], 0.f));
            __half2 v1 = __floats2half2_rn(fmaxf(acc[nt][mt][2], 0.f), fmaxf(acc[nt][mt][3], 0.f));
            *(__half2*)(Hout + r0 * sOut + n0 + 2 * tig) = v0;
            *(__half2*)(Hout + (r0 + 8) * sOut + n0 + 2 * tig) = v1;
        }
    }
}

// Layer 4 (100->256, no relu): fused einsum accumulated in registers,
// written as conflict-free float2 stores into this warp's MSGP partial buffer.
__device__ __forceinline__ void layer4_f16(
    const __half* __restrict__ Hin,
    const __half* __restrict__ W4h,
    const float* __restrict__ b4f,
    const float* __restrict__ XV,
    float* __restrict__ msgp,     // this warp's [32][18] partial buffer
    int q, int mbase, int lane)
{
    const int grp = lane >> 2, tig = lane & 3;
    float acc[8][2][4];
    #pragma unroll
    for (int nt = 0; nt < 8; nt++) {
        const int c = (q * 8 + nt) * 8 + 2 * tig;
        const float b0 = b4f[c], b1 = b4f[c + 1];
        #pragma unroll
        for (int mt = 0; mt < 2; mt++) {
            acc[nt][mt][0] = b0; acc[nt][mt][1] = b1;
            acc[nt][mt][2] = b0; acc[nt][mt][3] = b1;
        }
    }
    const int arow = mbase + ((lane >> 3) & 1) * 8 + (lane & 7);
    const int acol = (lane >> 4) * 8;
    const int brow = lane & 15;
    #pragma unroll
    for (int k = 0; k < 6; k++) {
        const int k0 = k * 16;
        uint32_t a[2][4];
        #pragma unroll
        for (int mt = 0; mt < 2; mt++) {
            uint32_t aaddr = smem_u32(Hin + (arow + mt * 16) * 120 + k0 + acol);
            LDSM_X4(a[mt], aaddr);
        }
        #pragma unroll
        for (int nt = 0; nt < 8; nt++) {
            const int n0 = (q * 8 + nt) * 8;
            uint32_t b[2];
            uint32_t baddr = smem_u32(W4h + (k0 + brow) * 264 + n0);
            LDSM_X2T(b, baddr);
            MMA16816(acc[nt][0], a[0], b);
            MMA16816(acc[nt][1], a[1], b);
        }
    }
    {   // k8 tail, k = 96..103
        const int k0 = 96;
        uint32_t a2[2][2];
        #pragma unroll
        for (int mt = 0; mt < 2; mt++) {
            uint32_t aaddr = smem_u32(Hin + (arow + mt * 16) * 120 + k0);
            LDSM_X2(a2[mt], aaddr);
        }
        #pragma unroll
        for (int nt = 0; nt < 8; nt++) {
            const int n0 = (q * 8 + nt) * 8;
            uint32_t b0;
            uint32_t baddr = smem_u32(W4h + (k0 + (lane & 7)) * 264 + n0);
            LDSM_X1T(b0, baddr);
            MMA1688(acc[nt][0], a2[0], b0);
            MMA1688(acc[nt][1], a2[1], b0);
        }
    }

    // hoisted XV loads: 4 edges x 4 i-values (broadcast across tig lanes)
    float xvr[4][4];
    #pragma unroll
    for (int mt = 0; mt < 2; mt++)
        #pragma unroll
        for (int h = 0; h < 2; h++) {
            const int e = mbase + mt * 16 + grp + 8 * h;
            #pragma unroll
            for (int ii = 0; ii < 4; ii++)
                xvr[mt * 2 + h][ii] = XV[e * 17 + 4 * q + ii];
        }

    // accumulate einsum: msgacc[edge-slot 4][o-parity 2][pair 2]
    float msgacc[4][2][2];
    #pragma unroll
    for (int s = 0; s < 4; s++)
        #pragma unroll
        for (int p = 0; p < 2; p++) { msgacc[s][p][0] = 0.f; msgacc[s][p][1] = 0.f; }
    #pragma unroll
    for (int nt = 0; nt < 8; nt++) {
        const int par = nt & 1;          // o-pair parity: o = 2tig (+8 if odd)
        const int ii = nt >> 1;          // i = 4q + ii
        #pragma unroll
        for (int mt = 0; mt < 2; mt++) {
            const float xv0 = xvr[mt * 2 + 0][ii];
            const float xv1 = xvr[mt * 2 + 1][ii];
            msgacc[mt * 2 + 0][par][0] += xv0 * acc[nt][mt][0];
            msgacc[mt * 2 + 0][par][1] += xv0 * acc[nt][mt][1];
            msgacc[mt * 2 + 1][par][0] += xv1 * acc[nt][mt][2];
            msgacc[mt * 2 + 1][par][1] += xv1 * acc[nt][mt][3];
        }
    }
    #pragma unroll
    for (int mt = 0; mt < 2; mt++)
        #pragma unroll
        for (int h = 0; h < 2; h++) {
            const int e_loc = mt * 16 + grp + 8 * h;
            #pragma unroll
            for (int par = 0; par < 2; par++) {
                float2 v = make_float2(msgacc[mt * 2 + h][par][0], msgacc[mt * 2 + h][par][1]);
                *(float2*)&msgp[e_loc * 18 + 2 * tig + 8 * par] = v;
            }
        }
}

extern __shared__ char smem[];

__global__ void __launch_bounds__(THREADS, 1)
edge_kernel(const float* __restrict__ x,
            const int* __restrict__ ei,
            const float* __restrict__ ea,
            const float* __restrict__ W1, const float* __restrict__ b1,
            const float* __restrict__ W2, const float* __restrict__ b2,
            const float* __restrict__ W3, const float* __restrict__ b3,
            const float* __restrict__ W4, const float* __restrict__ b4)
{
    const int tid = threadIdx.x;
    const int wid = tid >> 5, lane = tid & 31;
    const int q = wid & 3;
    const int g = wid >> 2;            // group 0/1 (independent after init)
    const int mbase = g * 32;
    const int tidg = tid & 127;
    const int barid = g + 1;

    __half* W1h = (__half*)(smem + SM_W1);
    __half* W2h = (__half*)(smem + SM_W2);
    __half* W3h = (__half*)(smem + SM_W3);
    __half* W4h = (__half*)(smem + SM_W4);
    __half* A0h = (__half*)(smem + SM_A0);
    __half* H1h = (__half*)(smem + SM_H1);
    __half* H2h = (__half*)(smem + SM_H2);
    float*  XV  = (float*)(smem + SM_XV);
    float*  MSGP = (float*)(smem + SM_MSGP);
    float*  B1f = (float*)(smem + SM_B1);
    float*  B2f = (float*)(smem + SM_B2);
    float*  B3f = (float*)(smem + SM_B3);
    float*  B4f = (float*)(smem + SM_B4);
    int*    DSTi = (int*)(smem + SM_IDX);
    int*    SRCi = (int*)(smem + SM_SRC);

    for (int i = tid; i < W_ZERO_U32; i += THREADS) ((uint32_t*)smem)[i] = 0;
    __syncthreads();
    for (int i = tid; i < 8 * 100; i += THREADS) {
        int k = i / 100, n = i % 100;
        W1h[k * 120 + n] = __float2half(W1[i]);
    }
    for (int i = tid; i < 100 * 100; i += THREADS) {
        int k = i / 100, n = i % 100;
        W2h[k * 120 + n] = __float2half(W2[i]);
        W3h[k * 120 + n] = __float2half(W3[i]);
    }
    for (int i = tid; i < 100 * 256; i += THREADS) {
        int k = i >> 8, n = i & 255;
        W4h[k * 264 + n] = __float2half(W4[i]);
    }
    for (int i = tid; i < 112; i += THREADS) {
        B1f[i] = (i < 100) ? b1[i] : 0.0f;
        B2f[i] = (i < 100) ? b2[i] : 0.0f;
        B3f[i] = (i < 100) ? b3[i] : 0.0f;
    }
    for (int i = tid; i < 256; i += THREADS) B4f[i] = b4[i];
    __syncthreads();

    static const int nt0s[4]  = {0, 4, 8, 11};
    static const int ntcs[4]  = {4, 4, 3, 3};
    const int nt0 = nt0s[q], ntc = ntcs[q];
    float* msgp_w = MSGP + (g * 4 + q) * 576;   // this warp's [32][18]
    float* msgp_g = MSGP + g * 4 * 576;         // group base

    const int e4 = tidg >> 2, c4 = tidg & 3;    // staging decomposition

    // ---- preamble prefetch for the first tile ----
    int pf_src = 0, pf_dst = 0;
    float2 pf_a0 = make_float2(0.f, 0.f);
    if (blockIdx.x < NT_TILES) {
        const int base = blockIdx.x * M_TILE + mbase;
        if (tidg < 32) {
            pf_src = ei[base + tidg];
            pf_dst = ei[N_EDGES + base + tidg];
        }
        pf_a0 = ((const float2*)ea)[(long)(base + e4) * 4 + c4];
    }

    for (int t = blockIdx.x; t < NT_TILES; t += GRID) {
        // staging writes from prefetch registers (no global latency here)
        if (tidg < 32) {
            SRCi[mbase + tidg] = pf_src;
            DSTi[mbase + tidg] = pf_dst;
        }
        {   // A0 cols (2*tidg)&7, (2*tidg)&7+1 of edge e4 (cols 8+ never read: L1 is k8)
            int k = (2 * tidg) & 7;
            *(__half2*)&A0h[(mbase + e4) * 24 + k] = __floats2half2_rn(pf_a0.x, pf_a0.y);
        }
        group_bar(barid);

        // issue x[src] gather now; consumed just before L4 (latency covered by L1-L3)
        const int srcn = SRCi[mbase + e4];
        const float4 xvv = ((const float4*)x)[(long)srcn * 4 + c4];

        layer_f16<0, 4, true>(A0h, 24,  W1h, 120, B1f, H1h, 120, nt0, ntc, mbase, lane);  // K=8
        group_bar(barid);
        layer_f16<6, 4, true>(H1h, 120, W2h, 120, B2f, H2h, 120, nt0, ntc, mbase, lane);

        // prefetch next tile's indices + attrs (overlaps with L3/L4 compute)
        {
            const int tn = t + GRID;
            if (tn < NT_TILES) {
                const int basen = tn * M_TILE + mbase;
                if (tidg < 32) {
                    pf_src = ei[basen + tidg];
                    pf_dst = ei[N_EDGES + basen + tidg];
                }
                pf_a0 = ((const float2*)ea)[(long)(basen + e4) * 4 + c4];
            }
        }
        group_bar(barid);
        layer_f16<6, 4, true>(H2h, 120, W3h, 120, B3f, H1h, 120, nt0, ntc, mbase, lane);

        {   // write XV (xvv long since landed)
            float* xr = &XV[(mbase + e4) * 17 + c4 * 4];
            xr[0] = xvv.x; xr[1] = xvv.y; xr[2] = xvv.z; xr[3] = xvv.w;
        }
        group_bar(barid);   // H1 (L3 out) + XV visible
        layer4_f16(H1h, W4h, B4f, XV, msgp_w, q, mbase, lane);
        group_bar(barid);

        // scatter: sum 4 warp partials, one global RED per (e,o)
        for (int i = tidg; i < 32 * 16; i += 128) {
            int e = i >> 4, o = i & 15;
            float s = msgp_g[e * 18 + o] + msgp_g[576 + e * 18 + o]
                    + msgp_g[1152 + e * 18 + o] + msgp_g[1728 + e * 18 + o];
            atomicAdd(&g_agg[(long)DSTi[mbase + e] * OUT_CH + o], s);
        }
        if (tidg < 32) atomicAdd(&g_cnt[DSTi[mbase + tidg]], 1.0f);
        group_bar(barid);
    }
}

__global__ void finalize_kernel(const float* __restrict__ x,
                                const float* __restrict__ root,
                                const float* __restrict__ bias,
                                float* __restrict__ out)
{
    int i = blockIdx.x * blockDim.x + threadIdx.x;
    if (i >= N_NODES * OUT_CH) return;
    int n = i >> 4, o = i & 15;
    float c = fmaxf(g_cnt[n], 1.0f);
    float acc = g_agg[i] / c + bias[o];
    const float* xr = x + (long)n * IN_CH;
    #pragma unroll
    for (int k = 0; k < IN_CH; k++)
        acc += xr[k] * root[k * OUT_CH + o];
    out[i] = acc;
}

extern "C" void kernel_launch(void* const* d_in, const int* in_sizes, int n_in,
                              void* d_out, int out_size) {
    const float* x    = (const float*)d_in[0];
    const int*   ei   = (const int*)d_in[1];
    const float* ea   = (const float*)d_in[2];
    const float* W1   = (const float*)d_in[3];
    const float* b1   = (const float*)d_in[4];
    const float* W2   = (const float*)d_in[5];
    const float* b2   = (const float*)d_in[6];
    const float* W3   = (const float*)d_in[7];
    const float* b3   = (const float*)d_in[8];
    const float* W4   = (const float*)d_in[9];
    const float* b4   = (const float*)d_in[10];
    const float* root = (const float*)d_in[11];
    const float* bias = (const float*)d_in[12];
    float* out = (float*)d_out;

    cudaFuncSetAttribute(edge_kernel, cudaFuncAttributeMaxDynamicSharedMemorySize, SMEM_BYTES);

    zero_kernel<<<1024, 256>>>();
    edge_kernel<<<GRID, THREADS, SMEM_BYTES>>>(x, ei, ea, W1, b1, W2, b2, W3, b3, W4, b4);
    finalize_kernel<<<(N_NODES * OUT_CH + 255) / 256, 256>>>(x, root, bias, out);
}

// round 11
// speedup vs baseline: 3.4528x; 1.4838x over previous
#include <cuda_runtime.h>
#include <cuda_fp16.h>
#include <cstdint>

#define N_NODES 50000
#define N_EDGES 800000
#define IN_CH 16
#define OUT_CH 16
#define M_TILE 96
#define NT_TILES ((N_EDGES + M_TILE - 1) / M_TILE)   // 8334
#define THREADS 384
#define GRID 152

// ---- smem byte offsets ----
#define SM_W1   0        // [16][120] f16   = 3840
#define SM_W2   3840     // [112][120] f16  = 26880
#define SM_W3   30720    // [112][120] f16  = 26880
#define SM_W4   57600    // [112][264] f16  = 59136
#define SM_A0   116736   // [96][24] f16    = 4608
#define SM_H1   121344   // [96][120] f16   = 23040
#define SM_H2   144384   // [96][120] f16   = 23040
#define SM_XV   167424   // [96][17] f32    = 6528
#define SM_MSGP 173952   // [12][16][18] f32 = 13824 (per-warp partials)
#define SM_B1   187776   // [112] f32
#define SM_B2   188224
#define SM_B3   188672
#define SM_B4   189120   // [256] f32
#define SM_IDX  190144   // dst [96] int
#define SM_SRC  190528   // src [96] int
#define SMEM_BYTES 190912
#define W_ZERO_U32 (116736 / 4)

__device__ float g_agg[N_NODES * OUT_CH];
__device__ float g_cnt[N_NODES];

__device__ __forceinline__ uint32_t smem_u32(const void* p) {
    uint32_t a;
    asm("{ .reg .u64 t; cvta.to.shared.u64 t, %1; cvt.u32.u64 %0, t; }" : "=r"(a) : "l"(p));
    return a;
}
__device__ __forceinline__ void group_bar(int id) {
    asm volatile("bar.sync %0, 128;" :: "r"(id) : "memory");
}

#define LDSM_X4(r, a) \
    asm volatile("ldmatrix.sync.aligned.m8n8.x4.shared.b16 {%0,%1,%2,%3}, [%4];" \
        : "=r"((r)[0]), "=r"((r)[1]), "=r"((r)[2]), "=r"((r)[3]) : "r"(a))
#define LDSM_X2(r, a) \
    asm volatile("ldmatrix.sync.aligned.m8n8.x2.shared.b16 {%0,%1}, [%2];" \
        : "=r"((r)[0]), "=r"((r)[1]) : "r"(a))
#define LDSM_X2T(r, a) \
    asm volatile("ldmatrix.sync.aligned.m8n8.x2.trans.shared.b16 {%0,%1}, [%2];" \
        : "=r"((r)[0]), "=r"((r)[1]) : "r"(a))
#define LDSM_X1T(r, a) \
    asm volatile("ldmatrix.sync.aligned.m8n8.x1.trans.shared.b16 {%0}, [%1];" \
        : "=r"(r) : "r"(a))
#define MMA16816(c, a, b) \
    asm volatile("mma.sync.aligned.m16n8k16.row.col.f32.f16.f16.f32 " \
        "{%0,%1,%2,%3},{%4,%5,%6,%7},{%8,%9},{%0,%1,%2,%3};" \
        : "+f"((c)[0]), "+f"((c)[1]), "+f"((c)[2]), "+f"((c)[3]) \
        : "r"((a)[0]), "r"((a)[1]), "r"((a)[2]), "r"((a)[3]), "r"((b)[0]), "r"((b)[1]))
#define MMA1688(c, a, b) \
    asm volatile("mma.sync.aligned.m16n8k8.row.col.f32.f16.f16.f32 " \
        "{%0,%1,%2,%3},{%4,%5},{%6},{%0,%1,%2,%3};" \
        : "+f"((c)[0]), "+f"((c)[1]), "+f"((c)[2]), "+f"((c)[3]) \
        : "r"((a)[0]), "r"((a)[1]), "r"(b))

__global__ void zero_kernel() {
    int total = N_NODES * OUT_CH;
    for (int i = blockIdx.x * blockDim.x + threadIdx.x; i < total; i += gridDim.x * blockDim.x) {
        g_agg[i] = 0.0f;
        if (i < N_NODES) g_cnt[i] = 0.0f;
    }
}

// MLP layer: Hout = relu(Hin @ W + b). Warp owns ONE 16-row m-tile (rows mrow..mrow+16)
// and ntc n-tiles starting at nt0. K = K16*16 (+8 if TAIL).
template<int K16, bool TAIL>
__device__ __forceinline__ void layer_f16(
    const __half* __restrict__ Hin, int sIn,
    const __half* __restrict__ W, int sW,
    const float* __restrict__ bias,
    __half* __restrict__ Hout, int sOut,
    int nt0, int ntc, int mrow, int lane)
{
    const int grp = lane >> 2, tig = lane & 3;
    float acc[7][4];
    #pragma unroll
    for (int j = 0; j < 7; j++) {
        if (j >= ntc) break;
        const int c = (nt0 + j) * 8 + 2 * tig;
        acc[j][0] = bias[c]; acc[j][1] = bias[c + 1];
        acc[j][2] = bias[c]; acc[j][3] = bias[c + 1];
    }
    const int arow = mrow + ((lane >> 3) & 1) * 8 + (lane & 7);
    const int acol = (lane >> 4) * 8;
    const int brow = lane & 15;
    #pragma unroll
    for (int k = 0; k < K16; k++) {
        const int k0 = k * 16;
        uint32_t a[4];
        LDSM_X4(a, smem_u32(Hin + arow * sIn + k0 + acol));
        #pragma unroll
        for (int j = 0; j < 7; j++) {
            if (j >= ntc) break;
            const int n0 = (nt0 + j) * 8;
            uint32_t b[2];
            LDSM_X2T(b, smem_u32(W + (k0 + brow) * sW + n0));
            MMA16816(acc[j], a, b);
        }
    }
    if (TAIL) {  // k8 step at k0 = K16*16
        const int k0 = K16 * 16;
        uint32_t a2[2];
        LDSM_X2(a2, smem_u32(Hin + arow * sIn + k0));
        #pragma unroll
        for (int j = 0; j < 7; j++) {
            if (j >= ntc) break;
            const int n0 = (nt0 + j) * 8;
            uint32_t b0;
            LDSM_X1T(b0, smem_u32(W + (k0 + (lane & 7)) * sW + n0));
            MMA1688(acc[j], a2, b0);
        }
    }
    #pragma unroll
    for (int j = 0; j < 7; j++) {
        if (j >= ntc) break;
        const int n0 = (nt0 + j) * 8;
        const int r0 = mrow + grp;
        __half2 v0 = __floats2half2_rn(fmaxf(acc[j][0], 0.f), fmaxf(acc[j][1], 0.f));
        __half2 v1 = __floats2half2_rn(fmaxf(acc[j][2], 0.f), fmaxf(acc[j][3], 0.f));
        *(__half2*)(Hout + r0 * sOut + n0 + 2 * tig) = v0;
        *(__half2*)(Hout + (r0 + 8) * sOut + n0 + 2 * tig) = v1;
    }
}

// Layer 4 (100->256, no relu): warp owns one 16-row m-tile and 16 n-tiles
// (half of 256 cols). Fused einsum in registers, float2 partial stores.
__device__ __forceinline__ void layer4_f16(
    const __half* __restrict__ Hin,
    const __half* __restrict__ W4h,
    const float* __restrict__ b4f,
    const float* __restrict__ XV,
    float* __restrict__ msgp,     // this warp's [16][18] partial buffer
    int nt0, int mrow, int lane)
{
    const int grp = lane >> 2, tig = lane & 3;
    float acc[16][4];
    #pragma unroll
    for (int j = 0; j < 16; j++) {
        const int c = (nt0 + j) * 8 + 2 * tig;
        acc[j][0] = b4f[c]; acc[j][1] = b4f[c + 1];
        acc[j][2] = b4f[c]; acc[j][3] = b4f[c + 1];
    }
    const int arow = mrow + ((lane >> 3) & 1) * 8 + (lane & 7);
    const int acol = (lane >> 4) * 8;
    const int brow = lane & 15;
    #pragma unroll
    for (int k = 0; k < 6; k++) {
        const int k0 = k * 16;
        uint32_t a[4];
        LDSM_X4(a, smem_u32(Hin + arow * 120 + k0 + acol));
        #pragma unroll
        for (int j = 0; j < 16; j++) {
            const int n0 = (nt0 + j) * 8;
            uint32_t b[2];
            LDSM_X2T(b, smem_u32(W4h + (k0 + brow) * 264 + n0));
            MMA16816(acc[j], a, b);
        }
    }
    {   // k8 tail, k = 96..103
        const int k0 = 96;
        uint32_t a2[2];
        LDSM_X2(a2, smem_u32(Hin + arow * 120 + k0));
        #pragma unroll
        for (int j = 0; j < 16; j++) {
            const int n0 = (nt0 + j) * 8;
            uint32_t b0;
            LDSM_X1T(b0, smem_u32(W4h + (k0 + (lane & 7)) * 264 + n0));
            MMA1688(acc[j], a2, b0);
        }
    }

    // XV: 2 edges (grp, grp+8) x 8 i-values (this warp's i-range = nt0/2 .. +8)
    const int i0 = nt0 >> 1;
    float xvr[2][8];
    #pragma unroll
    for (int h = 0; h < 2; h++) {
        const int e = mrow + grp + 8 * h;
        #pragma unroll
        for (int ii = 0; ii < 8; ii++)
            xvr[h][ii] = XV[e * 17 + i0 + ii];
    }
    // einsum accumulate: msgacc[h][par][2]
    float msgacc[2][2][2];
    #pragma unroll
    for (int h = 0; h < 2; h++)
        #pragma unroll
        for (int p = 0; p < 2; p++) { msgacc[h][p][0] = 0.f; msgacc[h][p][1] = 0.f; }
    #pragma unroll
    for (int j = 0; j < 16; j++) {
        const int par = j & 1;          // o = 2tig (+8 if odd)
        const int ii = j >> 1;
        msgacc[0][par][0] += xvr[0][ii] * acc[j][0];
        msgacc[0][par][1] += xvr[0][ii] * acc[j][1];
        msgacc[1][par][0] += xvr[1][ii] * acc[j][2];
        msgacc[1][par][1] += xvr[1][ii] * acc[j][3];
    }
    #pragma unroll
    for (int h = 0; h < 2; h++)
        #pragma unroll
        for (int par = 0; par < 2; par++) {
            float2 v = make_float2(msgacc[h][par][0], msgacc[h][par][1]);
            *(float2*)&msgp[(grp + 8 * h) * 18 + 2 * tig + 8 * par] = v;
        }
}

extern __shared__ char smem[];

__global__ void __launch_bounds__(THREADS, 1)
edge_kernel(const float* __restrict__ x,
            const int* __restrict__ ei,
            const float* __restrict__ ea,
            const float* __restrict__ W1, const float* __restrict__ b1,
            const float* __restrict__ W2, const float* __restrict__ b2,
            const float* __restrict__ W3, const float* __restrict__ b3,
            const float* __restrict__ W4, const float* __restrict__ b4)
{
    const int tid = threadIdx.x;
    const int wid = tid >> 5, lane = tid & 31;
    const int q = wid & 3;
    const int g = wid >> 2;            // group 0/1/2 (independent after init)
    const int mbase = g * 32;
    const int tidg = tid & 127;
    const int barid = g + 1;
    const int mrow = mbase + (q >> 1) * 16;   // this warp's 16 rows

    __half* W1h = (__half*)(smem + SM_W1);
    __half* W2h = (__half*)(smem + SM_W2);
    __half* W3h = (__half*)(smem + SM_W3);
    __half* W4h = (__half*)(smem + SM_W4);
    __half* A0h = (__half*)(smem + SM_A0);
    __half* H1h = (__half*)(smem + SM_H1);
    __half* H2h = (__half*)(smem + SM_H2);
    float*  XV  = (float*)(smem + SM_XV);
    float*  MSGP = (float*)(smem + SM_MSGP);
    float*  B1f = (float*)(smem + SM_B1);
    float*  B2f = (float*)(smem + SM_B2);
    float*  B3f = (float*)(smem + SM_B3);
    float*  B4f = (float*)(smem + SM_B4);
    int*    DSTi = (int*)(smem + SM_IDX);
    int*    SRCi = (int*)(smem + SM_SRC);

    for (int i = tid; i < W_ZERO_U32; i += THREADS) ((uint32_t*)smem)[i] = 0;
    __syncthreads();
    for (int i = tid; i < 8 * 100; i += THREADS) {
        int k = i / 100, n = i % 100;
        W1h[k * 120 + n] = __float2half(W1[i]);
    }
    for (int i = tid; i < 100 * 100; i += THREADS) {
        int k = i / 100, n = i % 100;
        W2h[k * 120 + n] = __float2half(W2[i]);
        W3h[k * 120 + n] = __float2half(W3[i]);
    }
    for (int i = tid; i < 100 * 256; i += THREADS) {
        int k = i >> 8, n = i & 255;
        W4h[k * 264 + n] = __float2half(W4[i]);
    }
    for (int i = tid; i < 112; i += THREADS) {
        B1f[i] = (i < 100) ? b1[i] : 0.0f;
        B2f[i] = (i < 100) ? b2[i] : 0.0f;
        B3f[i] = (i < 100) ? b3[i] : 0.0f;
    }
    for (int i = tid; i < 256; i += THREADS) B4f[i] = b4[i];
    __syncthreads();

    // L1-L3: 13 n-tiles split 7/6 by q parity; L4: 32 n-tiles split 16/16.
    const int nt0 = (q & 1) ? 7 : 0;
    const int ntc = (q & 1) ? 6 : 7;
    const int nt0_4 = (q & 1) * 16;
    float* msgp_w = MSGP + (g * 4 + q) * 288;           // this warp's [16][18]
    float* msgp_m = MSGP + (g * 4) * 288;               // group base

    const int e4 = tidg >> 2, c4 = tidg & 3;

    // ---- preamble prefetch for the first tile ----
    int pf_src = 0, pf_dst = 0;
    float2 pf_a0 = make_float2(0.f, 0.f);
    {
        const int base = blockIdx.x * M_TILE + mbase;
        if (base < N_EDGES) {
            if (tidg < 32) {
                pf_src = ei[base + tidg];
                pf_dst = ei[N_EDGES + base + tidg];
            }
            pf_a0 = ((const float2*)ea)[(long)(base + e4) * 4 + c4];
        }
    }

    for (int t = blockIdx.x; t < NT_TILES; t += GRID) {
        const int base = t * M_TILE + mbase;
        if (base >= N_EDGES) continue;   // whole group inactive for this tile

        if (tidg < 32) {
            SRCi[mbase + tidg] = pf_src;
            DSTi[mbase + tidg] = pf_dst;
        }
        {
            int k = (2 * tidg) & 7;
            *(__half2*)&A0h[(mbase + e4) * 24 + k] = __floats2half2_rn(pf_a0.x, pf_a0.y);
        }
        group_bar(barid);

        // x[src] gather issued now, consumed before L4
        const int srcn = SRCi[mbase + e4];
        const float4 xvv = ((const float4*)x)[(long)srcn * 4 + c4];

        layer_f16<0, true>(A0h, 24,  W1h, 120, B1f, H1h, 120, nt0, ntc, mrow, lane);  // K=8
        group_bar(barid);
        layer_f16<6, true>(H1h, 120, W2h, 120, B2f, H2h, 120, nt0, ntc, mrow, lane);

        // prefetch next active tile's indices + attrs
        {
            const int basen = (t + GRID) * M_TILE + mbase;
            if (basen < N_EDGES) {
                if (tidg < 32) {
                    pf_src = ei[basen + tidg];
                    pf_dst = ei[N_EDGES + basen + tidg];
                }
                pf_a0 = ((const float2*)ea)[(long)(basen + e4) * 4 + c4];
            }
        }
        group_bar(barid);
        layer_f16<6, true>(H2h, 120, W3h, 120, B3f, H1h, 120, nt0, ntc, mrow, lane);

        {   // write XV
            float* xr = &XV[(mbase + e4) * 17 + c4 * 4];
            xr[0] = xvv.x; xr[1] = xvv.y; xr[2] = xvv.z; xr[3] = xvv.w;
        }
        group_bar(barid);
        layer4_f16(H1h, W4h, B4f, XV, msgp_w, nt0_4, mrow, lane);
        group_bar(barid);

        // scatter: sum the 2 partials of this edge's m-tile warp pair
        for (int i = tidg; i < 32 * 16; i += 128) {
            int e = i >> 4, o = i & 15;
            int mt = e >> 4, r = e & 15;
            float s = msgp_m[(mt * 2 + 0) * 288 + r * 18 + o]
                    + msgp_m[(mt * 2 + 1) * 288 + r * 18 + o];
            atomicAdd(&g_agg[(long)DSTi[mbase + e] * OUT_CH + o], s);
        }
        if (tidg < 32) atomicAdd(&g_cnt[DSTi[mbase + tidg]], 1.0f);
        group_bar(barid);
    }
}

__global__ void finalize_kernel(const float* __restrict__ x,
                                const float* __restrict__ root,
                                const float* __restrict__ bias,
                                float* __restrict__ out)
{
    int i = blockIdx.x * blockDim.x + threadIdx.x;
    if (i >= N_NODES * OUT_CH) return;
    int n = i >> 4, o = i & 15;
    float c = fmaxf(g_cnt[n], 1.0f);
    float acc = g_agg[i] / c + bias[o];
    const float* xr = x + (long)n * IN_CH;
    #pragma unroll
    for (int k = 0; k < IN_CH; k++)
        acc += xr[k] * root[k * OUT_CH + o];
    out[i] = acc;
}

extern "C" void kernel_launch(void* const* d_in, const int* in_sizes, int n_in,
                              void* d_out, int out_size) {
    const float* x    = (const float*)d_in[0];
    const int*   ei   = (const int*)d_in[1];
    const float* ea   = (const float*)d_in[2];
    const float* W1   = (const float*)d_in[3];
    const float* b1   = (const float*)d_in[4];
    const float* W2   = (const float*)d_in[5];
    const float* b2   = (const float*)d_in[6];
    const float* W3   = (const float*)d_in[7];
    const float* b3   = (const float*)d_in[8];
    const float* W4   = (const float*)d_in[9];
    const float* b4   = (const float*)d_in[10];
    const float* root = (const float*)d_in[11];
    const float* bias = (const float*)d_in[12];
    float* out = (float*)d_out;

    cudaFuncSetAttribute(edge_kernel, cudaFuncAttributeMaxDynamicSharedMemorySize, SMEM_BYTES);

    zero_kernel<<<1024, 256>>>();
    edge_kernel<<<GRID, THREADS, SMEM_BYTES>>>(x, ei, ea, W1, b1, W2, b2, W3, b3, W4, b4);
    finalize_kernel<<<(N_NODES * OUT_CH + 255) / 256, 256>>>(x, root, bias, out);
}